// round 1
// baseline (speedup 1.0000x reference)
#include <cuda_runtime.h>
#include <cstdint>

#define BATCH 4096
#define SDIM  64
#define OUTD  12
#define BM    128   // batch rows per block
#define BK    16    // K tile

// Scratch ping-pong buffers (max layer width 256)
__device__ float g_buf0[BATCH * 256];
__device__ float g_buf1[BATCH * 256];

__device__ __forceinline__ float liquid_act(float v) {
    return tanhf(v) + 0.1f * sinf(0.5f * v) * cosf(0.3f * v);
}

// Fused: pre[b,n] = sum_s act( (x @ Wi[n])[b,s] + bi[n,s] + bl[n,s] ) * Wo[n,s] + bo[n]
// Block: BM=128 batch rows x one neuron n (S=64 cols). 256 threads.
// Thread tile: 4 rows x 8 cols (4 f32x2 pairs). tm = tid/8 (0..31), tc = tid%8.
__global__ __launch_bounds__(256)
void liquid_gemm_kernel(const float* __restrict__ x,    // [B,K]
                        const float* __restrict__ Wi,   // [N,K,S]
                        const float* __restrict__ bi,   // [N,S]
                        const float* __restrict__ bl,   // [N,S]
                        const float* __restrict__ Wo,   // [N,S]
                        const float* __restrict__ bo,   // [N]
                        float* __restrict__ pre,        // [B,N]
                        int K, int N)
{
    const int n   = blockIdx.y;
    const int b0  = blockIdx.x * BM;
    const int tid = threadIdx.x;
    const int tm  = tid >> 3;   // 0..31  -> rows 4*tm..4*tm+3
    const int tc  = tid & 7;    // 0..7   -> cols 8*tc..8*tc+7

    __shared__ __align__(16) float xs[BK][132];  // k-major, padded (132*4 % 16 == 0)
    __shared__ __align__(16) float ws[BK][66];   // padded   (66*4 % 8 == 0)

    unsigned long long acc[4][4];
    #pragma unroll
    for (int i = 0; i < 4; ++i)
        #pragma unroll
        for (int p = 0; p < 4; ++p) acc[i][p] = 0ull;

    const float* WiN = Wi + (size_t)n * K * SDIM;

    for (int k0 = 0; k0 < K; k0 += BK) {
        // Load X tile transposed: xs[k][r] = x[b0+r][k0+k]
        #pragma unroll
        for (int i = 0; i < (BM * BK) / 256; ++i) {
            int idx = tid + i * 256;
            int r = idx >> 4;
            int k = idx & 15;
            xs[k][r] = x[(size_t)(b0 + r) * K + (k0 + k)];
        }
        // Load Wi tile: ws[k][s] = Wi[n][k0+k][s]  (contiguous)
        #pragma unroll
        for (int i = 0; i < (BK * SDIM) / 256; ++i) {
            int idx = tid + i * 256;
            int k = idx >> 6;
            int s = idx & 63;
            ws[k][s] = WiN[(size_t)(k0 + k) * SDIM + s];
        }
        __syncthreads();

        #pragma unroll
        for (int k = 0; k < BK; ++k) {
            float4 a4 = *reinterpret_cast<const float4*>(&xs[k][4 * tm]);
            unsigned long long b2[4];
            #pragma unroll
            for (int p = 0; p < 4; ++p)
                b2[p] = *reinterpret_cast<const unsigned long long*>(&ws[k][8 * tc + 2 * p]);
            float av[4] = {a4.x, a4.y, a4.z, a4.w};
            #pragma unroll
            for (int i = 0; i < 4; ++i) {
                unsigned long long ap;
                asm("mov.b64 %0, {%1, %1};" : "=l"(ap) : "r"(__float_as_uint(av[i])));
                #pragma unroll
                for (int p = 0; p < 4; ++p)
                    asm("fma.rn.f32x2 %0, %1, %2, %0;" : "+l"(acc[i][p]) : "l"(ap), "l"(b2[p]));
            }
        }
        __syncthreads();
    }

    // Epilogue: +bias, activation, dot with Wo over s, reduce across tc lanes
    const float* biN = bi + (size_t)n * SDIM;
    const float* blN = bl + (size_t)n * SDIM;
    const float* WoN = Wo + (size_t)n * SDIM;

    float psum[4] = {0.f, 0.f, 0.f, 0.f};
    #pragma unroll
    for (int p = 0; p < 4; ++p) {
        int s = 8 * tc + 2 * p;
        float b0s = biN[s] + blN[s];
        float b1s = biN[s + 1] + blN[s + 1];
        float w0 = WoN[s], w1 = WoN[s + 1];
        #pragma unroll
        for (int i = 0; i < 4; ++i) {
            float v0 = __uint_as_float((unsigned)(acc[i][p] & 0xffffffffull)) + b0s;
            float v1 = __uint_as_float((unsigned)(acc[i][p] >> 32)) + b1s;
            psum[i] += liquid_act(v0) * w0 + liquid_act(v1) * w1;
        }
    }
    // reduce over the 8 tc lanes (contiguous lane segments of 8)
    #pragma unroll
    for (int off = 4; off > 0; off >>= 1)
        #pragma unroll
        for (int i = 0; i < 4; ++i)
            psum[i] += __shfl_down_sync(0xffffffffu, psum[i], off, 8);

    if (tc == 0) {
        float bon = bo[n];
        #pragma unroll
        for (int i = 0; i < 4; ++i) {
            int r = 4 * tm + i;
            pre[(size_t)(b0 + r) * N + n] = psum[i] + bon;
        }
    }
}

// h[b,n] = (pre[b,n] + 0.1 * sum_m pre[b,m] * L[m,n]) * a[n]
__global__ __launch_bounds__(256)
void lateral_kernel(const float* __restrict__ pre, const float* __restrict__ L,
                    const float* __restrict__ a, float* __restrict__ h, int N)
{
    const int b0  = blockIdx.x * 16;
    const int tid = threadIdx.x;
    __shared__ float ps[16 * 256];

    for (int idx = tid; idx < 16 * N; idx += 256)
        ps[idx] = pre[(size_t)(b0 + idx / N) * N + (idx % N)];
    __syncthreads();

    for (int idx = tid; idx < 16 * N; idx += 256) {
        int r = idx / N;
        int n = idx - r * N;
        const float* pr = ps + r * N;
        float sum = 0.f;
        #pragma unroll 4
        for (int m = 0; m < N; ++m)
            sum += pr[m] * L[(size_t)m * N + n];
        h[(size_t)(b0 + r) * N + n] = (pr[n] + 0.1f * sum) * a[n];
    }
}

// y[b,o] = h[b,:] @ Wout + bout
__global__ __launch_bounds__(256)
void out_kernel(const float* __restrict__ h, const float* __restrict__ Wout,
                const float* __restrict__ bout, float* __restrict__ y)
{
    int idx = blockIdx.x * blockDim.x + threadIdx.x;
    if (idx >= BATCH * OUTD) return;
    int b = idx / OUTD;
    int o = idx - b * OUTD;
    const float* hb = h + (size_t)b * 64;
    float s = bout[o];
    #pragma unroll
    for (int m = 0; m < 64; ++m)
        s += hb[m] * Wout[m * OUTD + o];
    y[idx] = s;
}

extern "C" void kernel_launch(void* const* d_in, const int* in_sizes, int n_in,
                              void* d_out, int out_size)
{
    (void)in_sizes; (void)n_in; (void)out_size;
    const float* x    = (const float*)d_in[0];
    // layer l params at base = 1 + 7*l : Wi, bi, bl, Wo, bo, L, a
    const float* Wi[3]; const float* bi[3]; const float* bl[3];
    const float* Wo[3]; const float* bo[3]; const float* Lm[3]; const float* ad[3];
    for (int l = 0; l < 3; ++l) {
        int base = 1 + 7 * l;
        Wi[l] = (const float*)d_in[base + 0];
        bi[l] = (const float*)d_in[base + 1];
        bl[l] = (const float*)d_in[base + 2];
        Wo[l] = (const float*)d_in[base + 3];
        bo[l] = (const float*)d_in[base + 4];
        Lm[l] = (const float*)d_in[base + 5];
        ad[l] = (const float*)d_in[base + 6];
    }
    const float* Wout = (const float*)d_in[22];
    const float* bout = (const float*)d_in[23];

    float* buf0 = nullptr; float* buf1 = nullptr;
    cudaGetSymbolAddress((void**)&buf0, g_buf0);
    cudaGetSymbolAddress((void**)&buf1, g_buf1);

    const int Ns[3] = {256, 128, 64};
    const int Ks[3] = {512, 256, 128};

    const float* cur_in = x;
    for (int l = 0; l < 3; ++l) {
        dim3 grid(BATCH / BM, Ns[l]);
        liquid_gemm_kernel<<<grid, 256>>>(cur_in, Wi[l], bi[l], bl[l], Wo[l], bo[l],
                                          buf0, Ks[l], Ns[l]);
        lateral_kernel<<<BATCH / 16, 256>>>(buf0, Lm[l], ad[l], buf1, Ns[l]);
        cur_in = buf1;
    }
    out_kernel<<<(BATCH * OUTD + 255) / 256, 256>>>(buf1, Wout, bout, (float*)d_out);
}